// round 6
// baseline (speedup 1.0000x reference)
#include <cuda_runtime.h>
#include <cstdint>

// Problem constants (fixed shapes per reference)
#define N_NODES  100000
#define D_FEAT   64
#define OUT_COLS 65
#define MAXDEG   48   // Poisson(12): P(deg>48) ~ 3e-15/node; rescan fallback keeps correctness regardless

// Static scratch (allocation-guard-safe; zero-initialized at module load,
// and accum_kernel restores g_count to zero after consuming it).
__device__ int  g_count[N_NODES];                       // per-node degree counters
__device__ int2 g_slots[(size_t)N_NODES * MAXDEG];      // {src_idx, bitcast(e_feat)}

// ---------------------------------------------------------------------------
// Kernel 1: bin edges by destination node into padded slots.
// One thread per edge (proven fastest shape). Int atomics only.
// Slots beyond MAXDEG are simply not written; accum's rescan path covers them.
// ---------------------------------------------------------------------------
__global__ void bin_kernel(const float* __restrict__ e_feat,
                           const int*   __restrict__ src_idx,
                           const int*   __restrict__ dst_idx,
                           int E) {
    int e = blockIdx.x * blockDim.x + threadIdx.x;
    if (e >= E) return;

    const int d = __ldg(dst_idx + e);
    const int pos = atomicAdd(&g_count[d], 1);
    if (pos < MAXDEG) {
        int2 se;
        se.x = __ldg(src_idx + e);
        se.y = __float_as_int(__ldg(e_feat + e));
        g_slots[(size_t)d * MAXDEG + pos] = se;
    }
}

// ---------------------------------------------------------------------------
// Kernel 2: accumulate. 16 lanes per node; lane l owns float4 chunk l.
// Slot pairs loaded as int4 (rows are 384B-aligned). Writes the FULL output
// row -> no output pre-zeroing needed. Resets g_count for the next replay.
//
// Fallback: if deg > MAXDEG (astronomically rare), recompute this node's sum
// by scanning the whole edge list (correct for any input).
// ---------------------------------------------------------------------------
__global__ void accum_kernel(const float* __restrict__ emb,
                             const float* __restrict__ e_feat,
                             const int*   __restrict__ src_idx,
                             const int*   __restrict__ dst_idx,
                             int E,
                             float* __restrict__ out) {
    const int t    = blockIdx.x * blockDim.x + threadIdx.x;
    const int node = t >> 4;
    const int lane = t & 15;
    if (node >= N_NODES) return;

    const int deg = g_count[node];
    if (lane == 0) g_count[node] = 0;   // self-clean for next call

    float4 acc = make_float4(0.f, 0.f, 0.f, 0.f);
    float  accE = 0.f;

    if (deg <= MAXDEG) {
        // Fast path: consume padded slots, 2 at a time via int4.
        const int4* slots2 =
            reinterpret_cast<const int4*>(g_slots + (size_t)node * MAXDEG);
        int j = 0;
        for (; j + 1 < deg; j += 2) {
            const int4 se = __ldg(slots2 + (j >> 1));   // {s0, f0, s1, f1}
            const float4 v0 = __ldg(reinterpret_cast<const float4*>(emb + (size_t)se.x * D_FEAT) + lane);
            const float4 v1 = __ldg(reinterpret_cast<const float4*>(emb + (size_t)se.z * D_FEAT) + lane);
            acc.x += v0.x + v1.x;
            acc.y += v0.y + v1.y;
            acc.z += v0.z + v1.z;
            acc.w += v0.w + v1.w;
            accE  += __int_as_float(se.y) + __int_as_float(se.w);
        }
        if (j < deg) {
            const int2 se = g_slots[(size_t)node * MAXDEG + j];
            const float4 v = __ldg(reinterpret_cast<const float4*>(emb + (size_t)se.x * D_FEAT) + lane);
            acc.x += v.x; acc.y += v.y; acc.z += v.z; acc.w += v.w;
            accE  += __int_as_float(se.y);
        }
    } else {
        // Rescan fallback (correctness-only; ~never executes).
        for (int e = 0; e < E; e++) {
            if (__ldg(dst_idx + e) == node) {
                const int s = __ldg(src_idx + e);
                const float4 v = __ldg(reinterpret_cast<const float4*>(emb + (size_t)s * D_FEAT) + lane);
                acc.x += v.x; acc.y += v.y; acc.z += v.z; acc.w += v.w;
                accE  += __ldg(e_feat + e);
            }
        }
    }

    float* row = out + (size_t)node * OUT_COLS + lane * 4;
    row[0] = acc.x;
    row[1] = acc.y;
    row[2] = acc.z;
    row[3] = acc.w;
    if (lane == 0) out[(size_t)node * OUT_COLS + D_FEAT] = accE;
}

// ---------------------------------------------------------------------------
// Launch: 2 kernels only.
// ---------------------------------------------------------------------------
extern "C" void kernel_launch(void* const* d_in, const int* in_sizes, int n_in,
                              void* d_out, int out_size) {
    const float* emb     = (const float*)d_in[0];   // [N, 64]
    const float* e_feat  = (const float*)d_in[1];   // [E]
    const int*   src_idx = (const int*)d_in[2];     // [E]
    const int*   dst_idx = (const int*)d_in[3];     // [E]
    float*       out     = (float*)d_out;           // [N, 65]

    const int E = in_sizes[1];

    // 1) bin edges by dst
    if (E > 0) {
        int threads = 256;
        int blocks  = (E + threads - 1) / threads;
        bin_kernel<<<blocks, threads>>>(e_feat, src_idx, dst_idx, E);
    }

    // 2) accumulate per node (writes full output, self-cleans counters)
    {
        const long long total = (long long)N_NODES * 16;
        int threads = 256;
        int blocks  = (int)((total + threads - 1) / threads);
        accum_kernel<<<blocks, threads>>>(emb, e_feat, src_idx, dst_idx, E, out);
    }
}

// round 7
// speedup vs baseline: 1.7846x; 1.7846x over previous
#include <cuda_runtime.h>
#include <cstdint>

// Problem constants (fixed shapes per reference)
#define N_NODES  100000
#define D_FEAT   64
#define OUT_COLS 65
#define MAXDEG   48            // Poisson(12): max deg over 100K nodes ~35-40; overflow path keeps correctness
#define OVF_CAP  1300000       // >= E, overflow list can never drop edges

// Static scratch (allocation-guard-safe). Zero at module load; the cleanup
// kernel restores the invariant (g_count==0, g_ovf_count==0) at the end of
// every call, so each kernel_launch invocation starts clean.
__device__ int  g_count[N_NODES];                       // per-node degree counters
__device__ int  g_ovf_count;                            // overflow edge count
__device__ int  g_done;                                 // tail-block arrival counter
__device__ int  g_ovf_edges[OVF_CAP];                   // overflow edge indices
__device__ int2 g_slots[(size_t)N_NODES * MAXDEG];      // {src_idx, bitcast(e_feat)}

// ---------------------------------------------------------------------------
// Kernel 1: bin edges by destination node into padded slots.
// One thread per edge (PROVEN fastest shape, ~21us). Int atomics only.
// ---------------------------------------------------------------------------
__global__ void bin_kernel(const float* __restrict__ e_feat,
                           const int*   __restrict__ src_idx,
                           const int*   __restrict__ dst_idx,
                           int E) {
    int e = blockIdx.x * blockDim.x + threadIdx.x;
    if (e >= E) return;

    const int d = __ldg(dst_idx + e);
    const int pos = atomicAdd(&g_count[d], 1);
    if (pos < MAXDEG) {
        int2 se;
        se.x = __ldg(src_idx + e);
        se.y = __float_as_int(__ldg(e_feat + e));
        g_slots[(size_t)d * MAXDEG + pos] = se;
    } else {
        int oi = atomicAdd(&g_ovf_count, 1);
        if (oi < OVF_CAP) g_ovf_edges[oi] = e;
    }
}

// ---------------------------------------------------------------------------
// Kernel 2: accumulate — EXACT R3 form (~21.5us, at the L2 gather roofline).
// 16 lanes per node; lane l owns float4 chunk l. Unroll-2, int2 slot loads.
// Read-only except the output row: NO counter writes, NO fallback branch
// (both measured to triple this kernel's time in R4/R6).
// ---------------------------------------------------------------------------
__global__ void accum_kernel(const float* __restrict__ emb,
                             float* __restrict__ out) {
    const int t    = blockIdx.x * blockDim.x + threadIdx.x;
    const int node = t >> 4;
    const int lane = t & 15;
    if (node >= N_NODES) return;

    int deg = g_count[node];
    if (deg > MAXDEG) deg = MAXDEG;

    const int2* slots = g_slots + (size_t)node * MAXDEG;

    float4 acc = make_float4(0.f, 0.f, 0.f, 0.f);
    float  accE = 0.f;

    int j = 0;
    for (; j + 1 < deg; j += 2) {
        const int2 se0 = slots[j];
        const int2 se1 = slots[j + 1];
        const float4 v0 = __ldg(reinterpret_cast<const float4*>(emb + (size_t)se0.x * D_FEAT) + lane);
        const float4 v1 = __ldg(reinterpret_cast<const float4*>(emb + (size_t)se1.x * D_FEAT) + lane);
        acc.x += v0.x + v1.x;
        acc.y += v0.y + v1.y;
        acc.z += v0.z + v1.z;
        acc.w += v0.w + v1.w;
        accE  += __int_as_float(se0.y) + __int_as_float(se1.y);
    }
    if (j < deg) {
        const int2 se = slots[j];
        const float4 v = __ldg(reinterpret_cast<const float4*>(emb + (size_t)se.x * D_FEAT) + lane);
        acc.x += v.x; acc.y += v.y; acc.z += v.z; acc.w += v.w;
        accE  += __int_as_float(se.y);
    }

    float* row = out + (size_t)node * OUT_COLS + lane * 4;
    row[0] = acc.x;
    row[1] = acc.y;
    row[2] = acc.z;
    row[3] = acc.w;
    if (lane == 0) out[(size_t)node * OUT_COLS + D_FEAT] = accE;
}

// ---------------------------------------------------------------------------
// Kernel 3: cleanup = overflow fix-up (normally no-op) + zero g_count for the
// next call. g_ovf_count/g_done are reset by the LAST block to finish
// (arrival counter), so every block has already read g_ovf_count — strictly
// correct for any input, no racy reset.
// ---------------------------------------------------------------------------
__global__ void cleanup_kernel(const float* __restrict__ emb,
                               const float* __restrict__ e_feat,
                               const int*   __restrict__ src_idx,
                               const int*   __restrict__ dst_idx,
                               float* __restrict__ out) {
    // --- overflow fix-up (reads g_ovf_count; no-op when 0) ---
    int n = g_ovf_count;
    if (n > OVF_CAP) n = OVF_CAP;
    const int total = n * 16;
    for (int t = blockIdx.x * blockDim.x + threadIdx.x; t < total;
         t += gridDim.x * blockDim.x) {
        const int i    = t >> 4;
        const int lane = t & 15;
        const int e = g_ovf_edges[i];
        const int s = src_idx[e];
        const int d = dst_idx[e];
        const float4 v = __ldg(reinterpret_cast<const float4*>(emb + (size_t)s * D_FEAT) + lane);
        float* row = out + (size_t)d * OUT_COLS + lane * 4;
        atomicAdd(row + 0, v.x);
        atomicAdd(row + 1, v.y);
        atomicAdd(row + 2, v.z);
        atomicAdd(row + 3, v.w);
        if (lane == 0) atomicAdd(out + (size_t)d * OUT_COLS + D_FEAT, e_feat[e]);
    }

    // --- zero counters for the next call (coalesced grid-stride) ---
    for (int i = blockIdx.x * blockDim.x + threadIdx.x; i < N_NODES;
         i += gridDim.x * blockDim.x) {
        g_count[i] = 0;
    }

    // --- last-block-out resets the scalars ---
    __syncthreads();
    if (threadIdx.x == 0) {
        __threadfence();
        int arrived = atomicAdd(&g_done, 1);
        if (arrived == (int)gridDim.x - 1) {
            g_ovf_count = 0;
            g_done = 0;
            __threadfence();
        }
    }
}

// ---------------------------------------------------------------------------
// Launch: 3 kernels.
// ---------------------------------------------------------------------------
extern "C" void kernel_launch(void* const* d_in, const int* in_sizes, int n_in,
                              void* d_out, int out_size) {
    const float* emb     = (const float*)d_in[0];   // [N, 64]
    const float* e_feat  = (const float*)d_in[1];   // [E]
    const int*   src_idx = (const int*)d_in[2];     // [E]
    const int*   dst_idx = (const int*)d_in[3];     // [E]
    float*       out     = (float*)d_out;           // [N, 65]

    const int E = in_sizes[1];

    // 1) bin edges by dst
    if (E > 0) {
        int threads = 256;
        int blocks  = (E + threads - 1) / threads;
        bin_kernel<<<blocks, threads>>>(e_feat, src_idx, dst_idx, E);
    }

    // 2) accumulate per node (writes full output; read-only otherwise)
    {
        const long long total = (long long)N_NODES * 16;
        int threads = 256;
        int blocks  = (int)((total + threads - 1) / threads);
        accum_kernel<<<blocks, threads>>>(emb, out);
    }

    // 3) cleanup: overflow fix-up (normally no-op) + zero counters
    {
        cleanup_kernel<<<128, 256>>>(emb, e_feat, src_idx, dst_idx, out);
    }
}

// round 8
// speedup vs baseline: 1.8555x; 1.0397x over previous
#include <cuda_runtime.h>
#include <cstdint>

// Problem constants (fixed shapes per reference)
#define N_NODES  100000
#define D_FEAT   64
#define OUT_COLS 65
#define MAXDEG   48            // Poisson(12): max deg over 100K nodes ~35-40; overflow path keeps correctness
#define OVF_CAP  1300000       // >= E, overflow list can never drop edges

// Static scratch (allocation-guard-safe)
__device__ int  g_count[N_NODES];                       // per-node degree counters
__device__ int  g_ovf_count;                            // overflow edge count
__device__ int  g_ovf_edges[OVF_CAP];                   // overflow edge indices
__device__ int2 g_slots[(size_t)N_NODES * MAXDEG];      // {src_idx, bitcast(e_feat)}

// ---------------------------------------------------------------------------
// Kernel 1: zero counters
// ---------------------------------------------------------------------------
__global__ void zero_counters_kernel() {
    int i = blockIdx.x * blockDim.x + threadIdx.x;
    if (i < N_NODES) g_count[i] = 0;
    if (i == 0) g_ovf_count = 0;
}

// ---------------------------------------------------------------------------
// Kernel 2: bin edges by destination (PROVEN shape, ~21us).
// PDL: the three input loads are independent of the zero pass, so issue them
// BEFORE cudaGridDependencySynchronize() to overlap with kernel 1's drain.
// ---------------------------------------------------------------------------
__global__ void bin_kernel(const float* __restrict__ e_feat,
                           const int*   __restrict__ src_idx,
                           const int*   __restrict__ dst_idx,
                           int E) {
    int e = blockIdx.x * blockDim.x + threadIdx.x;

    int d = 0, s = 0; float f = 0.f;
    const bool active = (e < E);
    if (active) {
        d = __ldg(dst_idx + e);
        s = __ldg(src_idx + e);
        f = __ldg(e_feat + e);
    }

    // Wait for zero_counters_kernel to fully complete (auto-trigger at its end)
    cudaGridDependencySynchronize();

    if (!active) return;

    const int pos = atomicAdd(&g_count[d], 1);
    if (pos < MAXDEG) {
        g_slots[(size_t)d * MAXDEG + pos] = make_int2(s, __float_as_int(f));
    } else {
        int oi = atomicAdd(&g_ovf_count, 1);
        if (oi < OVF_CAP) g_ovf_edges[oi] = e;
    }
}

// ---------------------------------------------------------------------------
// Kernel 3: accumulate — EXACT R3 form (~21.5us, at the L2 gather roofline).
// Read-only except the output row (counter write-back measured catastrophic).
// ---------------------------------------------------------------------------
__global__ void accum_kernel(const float* __restrict__ emb,
                             float* __restrict__ out) {
    const int t    = blockIdx.x * blockDim.x + threadIdx.x;
    const int node = t >> 4;
    const int lane = t & 15;

    // Everything here depends on bin; sync first (overlaps launch ramp only)
    cudaGridDependencySynchronize();

    if (node >= N_NODES) return;

    int deg = g_count[node];
    if (deg > MAXDEG) deg = MAXDEG;

    const int2* slots = g_slots + (size_t)node * MAXDEG;

    float4 acc = make_float4(0.f, 0.f, 0.f, 0.f);
    float  accE = 0.f;

    int j = 0;
    for (; j + 1 < deg; j += 2) {
        const int2 se0 = slots[j];
        const int2 se1 = slots[j + 1];
        const float4 v0 = __ldg(reinterpret_cast<const float4*>(emb + (size_t)se0.x * D_FEAT) + lane);
        const float4 v1 = __ldg(reinterpret_cast<const float4*>(emb + (size_t)se1.x * D_FEAT) + lane);
        acc.x += v0.x + v1.x;
        acc.y += v0.y + v1.y;
        acc.z += v0.z + v1.z;
        acc.w += v0.w + v1.w;
        accE  += __int_as_float(se0.y) + __int_as_float(se1.y);
    }
    if (j < deg) {
        const int2 se = slots[j];
        const float4 v = __ldg(reinterpret_cast<const float4*>(emb + (size_t)se.x * D_FEAT) + lane);
        acc.x += v.x; acc.y += v.y; acc.z += v.z; acc.w += v.w;
        accE  += __int_as_float(se.y);
    }

    float* row = out + (size_t)node * OUT_COLS + lane * 4;
    row[0] = acc.x;
    row[1] = acc.y;
    row[2] = acc.z;
    row[3] = acc.w;
    if (lane == 0) out[(size_t)node * OUT_COLS + D_FEAT] = accE;
}

// ---------------------------------------------------------------------------
// Kernel 4: overflow fix-up (normally a no-op).
// ---------------------------------------------------------------------------
__global__ void ovf_fix_kernel(const float* __restrict__ emb,
                               const float* __restrict__ e_feat,
                               const int*   __restrict__ src_idx,
                               const int*   __restrict__ dst_idx,
                               float* __restrict__ out) {
    cudaGridDependencySynchronize();

    int n = g_ovf_count;
    if (n > OVF_CAP) n = OVF_CAP;
    const int total = n * 16;
    for (int t = blockIdx.x * blockDim.x + threadIdx.x; t < total;
         t += gridDim.x * blockDim.x) {
        const int i    = t >> 4;
        const int lane = t & 15;
        const int e = g_ovf_edges[i];
        const int s = src_idx[e];
        const int d = dst_idx[e];
        const float4 v = __ldg(reinterpret_cast<const float4*>(emb + (size_t)s * D_FEAT) + lane);
        float* row = out + (size_t)d * OUT_COLS + lane * 4;
        atomicAdd(row + 0, v.x);
        atomicAdd(row + 1, v.y);
        atomicAdd(row + 2, v.z);
        atomicAdd(row + 3, v.w);
        if (lane == 0) atomicAdd(out + (size_t)d * OUT_COLS + D_FEAT, e_feat[e]);
    }
}

// ---------------------------------------------------------------------------
// PDL launch helper: downstream kernels allow programmatic serialization so
// their ramp overlaps the producer's drain. Semantics unchanged (consumers
// gridDepSync before touching producer data; auto-trigger at producer end
// implies full visibility).
// ---------------------------------------------------------------------------
template <typename... Args>
static void launch_pdl(void (*kern)(Args...), dim3 grid, dim3 block,
                       Args... args) {
    cudaLaunchConfig_t cfg = {};
    cfg.gridDim  = grid;
    cfg.blockDim = block;
    cfg.dynamicSmemBytes = 0;
    cfg.stream = 0;
    cudaLaunchAttribute attr[1];
    attr[0].id = cudaLaunchAttributeProgrammaticStreamSerialization;
    attr[0].val.programmaticStreamSerializationAllowed = 1;
    cfg.attrs = attr;
    cfg.numAttrs = 1;
    cudaLaunchKernelEx(&cfg, kern, args...);
}

extern "C" void kernel_launch(void* const* d_in, const int* in_sizes, int n_in,
                              void* d_out, int out_size) {
    const float* emb     = (const float*)d_in[0];   // [N, 64]
    const float* e_feat  = (const float*)d_in[1];   // [E]
    const int*   src_idx = (const int*)d_in[2];     // [E]
    const int*   dst_idx = (const int*)d_in[3];     // [E]
    float*       out     = (float*)d_out;           // [N, 65]

    const int E = in_sizes[1];

    // 1) zero counters (plain launch)
    {
        int threads = 256;
        int blocks  = (N_NODES + threads - 1) / threads;
        zero_counters_kernel<<<blocks, threads>>>();
    }

    // 2) bin edges by dst (PDL: overlaps zero's drain)
    if (E > 0) {
        int threads = 256;
        int blocks  = (E + threads - 1) / threads;
        launch_pdl(bin_kernel, dim3(blocks), dim3(threads),
                   e_feat, src_idx, dst_idx, E);
    }

    // 3) accumulate per node (PDL: overlaps bin's drain)
    {
        const long long total = (long long)N_NODES * 16;
        int threads = 256;
        int blocks  = (int)((total + threads - 1) / threads);
        launch_pdl(accum_kernel, dim3(blocks), dim3(threads), emb, out);
    }

    // 4) overflow fix-up (PDL; normally no-op)
    if (E > 0) {
        launch_pdl(ovf_fix_kernel, dim3(64), dim3(256),
                   emb, e_feat, src_idx, dst_idx, out);
    }
}